// round 2
// baseline (speedup 1.0000x reference)
#include <cuda_runtime.h>
#include <math.h>

#define BATCH 16
#define CB    256
#define CS    512
#define HID   512
#define IMG_H 128
#define IMG_W 128
#define H2    64
#define W2    64

#define TOKS_HF (BATCH*1024)          // 16384 tokens per band
#define ROWS_HF (3*TOKS_HF)           // 49152
#define ROWS_LF (BATCH*256)           // 4096

// scratch (device globals: no allocations allowed)
__device__ float g_z[(size_t)ROWS_HF*CB];      // 48 MiB  token abs-means, 3 bands
__device__ float g_p[(size_t)ROWS_LF*CS];      // 8 MiB   pooled x_small
__device__ float g_alpha[ROWS_HF];             // per-token alpha (3 bands)
__device__ float g_gate[(size_t)ROWS_LF*CB];   // 4 MiB   per-token per-channel gate

// ---------------------------------------------------------------------------
// Kernel 1: Z tokens from x_big. token(th,tw) covers a 4x4 pixel block.
// CTA = (b, th-row). smem transpose for coalesced writes.
// ---------------------------------------------------------------------------
__global__ __launch_bounds__(256) void k_zband(const float* __restrict__ xb) {
    __shared__ float zs[3][32][65];
    int b   = blockIdx.x >> 5;
    int th  = blockIdx.x & 31;
    int tid = threadIdx.x;
    int lane = tid & 31;      // tw
    int warp = tid >> 5;      // 8 warps
    const float* pb = xb + (size_t)b * CB * IMG_H * IMG_W
                         + (size_t)(th * 4) * IMG_W + lane * 4;
    size_t zrow0 = ((size_t)b * 1024 + th * 32);

    for (int cc = 0; cc < 4; cc++) {          // 4 chunks of 64 channels
        #pragma unroll
        for (int ci = 0; ci < 8; ci++) {
            int cl = warp * 8 + ci;           // 0..63
            int c  = cc * 64 + cl;
            const float* p = pb + (size_t)c * (IMG_H * IMG_W);
            float4 r0 = *(const float4*)(p);
            float4 r1 = *(const float4*)(p + IMG_W);
            float4 r2 = *(const float4*)(p + 2 * IMG_W);
            float4 r3 = *(const float4*)(p + 3 * IMG_W);
            float zh = fabsf(r0.x - r0.y + r1.x - r1.y)
                     + fabsf(r0.z - r0.w + r1.z - r1.w)
                     + fabsf(r2.x - r2.y + r3.x - r3.y)
                     + fabsf(r2.z - r2.w + r3.z - r3.w);
            float zv = fabsf(r0.x + r0.y - r1.x - r1.y)
                     + fabsf(r0.z + r0.w - r1.z - r1.w)
                     + fabsf(r2.x + r2.y - r3.x - r3.y)
                     + fabsf(r2.z + r2.w - r3.z - r3.w);
            float zd = fabsf(r0.x - r0.y - r1.x + r1.y)
                     + fabsf(r0.z - r0.w - r1.z + r1.w)
                     + fabsf(r2.x - r2.y - r3.x + r3.y)
                     + fabsf(r2.z - r2.w - r3.z + r3.w);
            zs[0][lane][cl] = zh * 0.0625f;
            zs[1][lane][cl] = zv * 0.0625f;
            zs[2][lane][cl] = zd * 0.0625f;
        }
        __syncthreads();
        for (int i = tid; i < 3 * 32 * 64; i += 256) {
            int band = i >> 11;
            int rem  = i & 2047;
            int t    = rem >> 6;
            int clx  = rem & 63;
            g_z[(size_t)band * TOKS_HF * CB + (zrow0 + t) * CB + cc * 64 + clx]
                = zs[band][t][clx];
        }
        __syncthreads();
    }
}

// ---------------------------------------------------------------------------
// Kernel 2: pooled x_small  P[b*256+t][s] = mean over 4x4.  CTA = (b, th).
// ---------------------------------------------------------------------------
__global__ __launch_bounds__(256) void k_pool(const float* __restrict__ xs) {
    __shared__ float ps[16][65];
    int b   = blockIdx.x >> 4;
    int th  = blockIdx.x & 15;
    int tid = threadIdx.x;
    int lane = tid & 31;
    int warp = tid >> 5;
    const float* pb = xs + (size_t)b * CS * H2 * W2
                         + (size_t)(th * 4) * W2 + lane * 2;
    size_t prow0 = ((size_t)b * 256 + th * 16);

    for (int cc = 0; cc < 8; cc++) {          // 8 chunks of 64 channels
        #pragma unroll
        for (int ci = 0; ci < 8; ci++) {
            int cl = warp * 8 + ci;
            int c  = cc * 64 + cl;
            const float* p = pb + (size_t)c * (H2 * W2);
            float s = 0.f;
            #pragma unroll
            for (int r = 0; r < 4; r++) {
                float2 v = *(const float2*)(p + r * W2);
                s += v.x + v.y;
            }
            s += __shfl_xor_sync(0xffffffffu, s, 1);
            if ((lane & 1) == 0) ps[lane >> 1][cl] = s * (1.0f / 16.0f);
        }
        __syncthreads();
        for (int i = tid; i < 16 * 64; i += 256) {
            int t = i >> 6, clx = i & 63;
            g_p[(prow0 + t) * CS + cc * 64 + clx] = ps[t][clx];
        }
        __syncthreads();
    }
}

// ---------------------------------------------------------------------------
// Kernel 3: hf fused MLP.  CTA = 32 token rows.
// GEMM1 (K=256,N=512) -> +b1 -> LN -> GEMM2 (K=512,N=256) -> cosine vs prompt
// smem: lnH[32*512] | Bs[16*512] (overlaid by reduce partials) | As[16*32] | npr
// ---------------------------------------------------------------------------
#define SMEM_HF_FLOATS (32*512 + 16*512 + 16*32 + 16)
#define SMEM_HF_BYTES  (SMEM_HF_FLOATS * 4)

__global__ __launch_bounds__(256, 2) void k_hf(
    const float* __restrict__ w1, const float* __restrict__ b1,
    const float* __restrict__ lnw, const float* __restrict__ lnb,
    const float* __restrict__ w2, const float* __restrict__ b2,
    const float* __restrict__ prompt)
{
    extern __shared__ float sm[];
    float* lnH  = sm;                     // 32*512
    float* Bs   = sm + 32 * 512;          // 16*512
    float* As   = Bs + 16 * 512;          // 16*32
    float* s_npr = As + 16 * 32;
    float* dotp = Bs;                     // overlay after GEMM2
    float* nqp  = Bs + 32 * 64;

    int tid = threadIdx.x;
    int lane = tid & 31, warp = tid >> 5;
    int tx = tid & 63, ty = tid >> 6;     // ty in 0..3 (8 rows), tx 0..63
    int row0 = blockIdx.x * 32;

    if (warp == 0) {
        float s = 0.f;
        #pragma unroll
        for (int i = 0; i < 8; i++) { float v = prompt[lane + 32 * i]; s += v * v; }
        #pragma unroll
        for (int off = 16; off > 0; off >>= 1) s += __shfl_xor_sync(0xffffffffu, s, off);
        if (lane == 0) *s_npr = sqrtf(s);
    }

    // ---- GEMM1: [32x512] = Z[32x256] @ w1 ----
    float acc[8][8];
    #pragma unroll
    for (int i = 0; i < 8; i++)
        #pragma unroll
        for (int j = 0; j < 8; j++) acc[i][j] = 0.f;

    for (int k0 = 0; k0 < 256; k0 += 16) {
        __syncthreads();
        if (tid < 128) {
            int m = tid >> 2, kk = (tid & 3) * 4;
            float4 v = *(const float4*)(g_z + (size_t)(row0 + m) * 256 + k0 + kk);
            As[(kk + 0) * 32 + m] = v.x;
            As[(kk + 1) * 32 + m] = v.y;
            As[(kk + 2) * 32 + m] = v.z;
            As[(kk + 3) * 32 + m] = v.w;
        }
        for (int i = tid; i < 2048; i += 256) {
            int kk = i >> 7, cp = (i & 127) << 2;
            *(float4*)(Bs + kk * 512 + cp) =
                *(const float4*)(w1 + (size_t)(k0 + kk) * 512 + cp);
        }
        __syncthreads();
        #pragma unroll
        for (int kk = 0; kk < 16; kk++) {
            float a[8], bb[8];
            #pragma unroll
            for (int i = 0; i < 8; i++) a[i] = As[kk * 32 + ty * 8 + i];
            #pragma unroll
            for (int j = 0; j < 8; j++) bb[j] = Bs[kk * 512 + tx + 64 * j];
            #pragma unroll
            for (int i = 0; i < 8; i++)
                #pragma unroll
                for (int j = 0; j < 8; j++) acc[i][j] += a[i] * bb[j];
        }
    }
    #pragma unroll
    for (int j = 0; j < 8; j++) {
        float bv = b1[tx + 64 * j];
        #pragma unroll
        for (int i = 0; i < 8; i++)
            lnH[(ty * 8 + i) * 512 + tx + 64 * j] = acc[i][j] + bv;
    }
    __syncthreads();

    // ---- LayerNorm per row (two-pass, matches reference) ----
    for (int rr = 0; rr < 4; rr++) {
        int r = warp * 4 + rr;
        float s = 0.f;
        #pragma unroll
        for (int i = 0; i < 16; i++) s += lnH[r * 512 + lane + 32 * i];
        #pragma unroll
        for (int off = 16; off > 0; off >>= 1) s += __shfl_xor_sync(0xffffffffu, s, off);
        float m = s * (1.0f / 512.0f);
        float v = 0.f;
        #pragma unroll
        for (int i = 0; i < 16; i++) {
            float d = lnH[r * 512 + lane + 32 * i] - m; v += d * d;
        }
        #pragma unroll
        for (int off = 16; off > 0; off >>= 1) v += __shfl_xor_sync(0xffffffffu, v, off);
        float inv = rsqrtf(v * (1.0f / 512.0f) + 1e-5f);
        #pragma unroll
        for (int i = 0; i < 16; i++) {
            int c = lane + 32 * i;
            float x = lnH[r * 512 + c];
            lnH[r * 512 + c] = (x - m) * inv * lnw[c] + lnb[c];
        }
    }
    __syncthreads();

    // ---- GEMM2: [32x256] = lnH[32x512] @ w2, fused cosine epilogue ----
    float ac2[8][4];
    #pragma unroll
    for (int i = 0; i < 8; i++)
        #pragma unroll
        for (int j = 0; j < 4; j++) ac2[i][j] = 0.f;

    for (int k0 = 0; k0 < 512; k0 += 16) {
        __syncthreads();
        for (int i = tid; i < 1024; i += 256) {
            int kk = i >> 6, cp = (i & 63) << 2;
            *(float4*)(Bs + kk * 256 + cp) =
                *(const float4*)(w2 + (size_t)(k0 + kk) * 256 + cp);
        }
        __syncthreads();
        #pragma unroll
        for (int kk = 0; kk < 16; kk++) {
            float a[8], bb[4];
            #pragma unroll
            for (int i = 0; i < 8; i++) a[i] = lnH[(ty * 8 + i) * 512 + k0 + kk];
            #pragma unroll
            for (int j = 0; j < 4; j++) bb[j] = Bs[kk * 256 + tx + 64 * j];
            #pragma unroll
            for (int i = 0; i < 8; i++)
                #pragma unroll
                for (int j = 0; j < 4; j++) ac2[i][j] += a[i] * bb[j];
        }
    }
    __syncthreads();   // before overlaying Bs with partials

    #pragma unroll
    for (int i = 0; i < 8; i++) {
        float dsum = 0.f, nsum = 0.f;
        #pragma unroll
        for (int j = 0; j < 4; j++) {
            int c = tx + 64 * j;
            float q = ac2[i][j] + b2[c];
            dsum += q * prompt[c];
            nsum += q * q;
        }
        dotp[(ty * 8 + i) * 64 + tx] = dsum;
        nqp [(ty * 8 + i) * 64 + tx] = nsum;
    }
    __syncthreads();
    for (int rr = 0; rr < 4; rr++) {
        int r = warp * 4 + rr;
        float d = dotp[r * 64 + lane] + dotp[r * 64 + lane + 32];
        float n = nqp [r * 64 + lane] + nqp [r * 64 + lane + 32];
        #pragma unroll
        for (int off = 16; off > 0; off >>= 1) {
            d += __shfl_xor_sync(0xffffffffu, d, off);
            n += __shfl_xor_sync(0xffffffffu, n, off);
        }
        if (lane == 0) {
            float sim = d / (fmaxf(sqrtf(n), 1e-8f) * fmaxf(*s_npr, 1e-8f));
            g_alpha[row0 + r] = fmaxf(sim, 0.0f);
        }
    }
}

// ---------------------------------------------------------------------------
// Kernel 4: lf fused chain. CTA = 32 token rows.
// kt = P @ low_w + low_b ;  h = kt @ w1 + b1 ; LN ; gate = sigmoid(h @ w2 + b2)
// ---------------------------------------------------------------------------
#define SMEM_LF_FLOATS (32*256 + 32*512 + 16*512 + 16*32 + 16)
#define SMEM_LF_BYTES  (SMEM_LF_FLOATS * 4)

__global__ __launch_bounds__(256, 1) void k_lf(
    const float* __restrict__ loww, const float* __restrict__ lowb,
    const float* __restrict__ w1, const float* __restrict__ b1,
    const float* __restrict__ lnw, const float* __restrict__ lnb,
    const float* __restrict__ w2, const float* __restrict__ b2)
{
    extern __shared__ float sm[];
    float* kt  = sm;                         // 32*256
    float* lnH = sm + 32 * 256;              // 32*512
    float* Bs  = lnH + 32 * 512;             // 16*512
    float* As  = Bs + 16 * 512;              // 16*32

    int tid = threadIdx.x;
    int lane = tid & 31, warp = tid >> 5;
    int tx = tid & 63, ty = tid >> 6;
    int row0 = blockIdx.x * 32;

    // ---- GEMM0: kt[32x256] = P[32x512] @ loww ----
    float ac0[8][4];
    #pragma unroll
    for (int i = 0; i < 8; i++)
        #pragma unroll
        for (int j = 0; j < 4; j++) ac0[i][j] = 0.f;

    for (int k0 = 0; k0 < 512; k0 += 16) {
        __syncthreads();
        if (tid < 128) {
            int m = tid >> 2, kk = (tid & 3) * 4;
            float4 v = *(const float4*)(g_p + (size_t)(row0 + m) * 512 + k0 + kk);
            As[(kk + 0) * 32 + m] = v.x;
            As[(kk + 1) * 32 + m] = v.y;
            As[(kk + 2) * 32 + m] = v.z;
            As[(kk + 3) * 32 + m] = v.w;
        }
        for (int i = tid; i < 1024; i += 256) {
            int kk = i >> 6, cp = (i & 63) << 2;
            *(float4*)(Bs + kk * 256 + cp) =
                *(const float4*)(loww + (size_t)(k0 + kk) * 256 + cp);
        }
        __syncthreads();
        #pragma unroll
        for (int kk = 0; kk < 16; kk++) {
            float a[8], bb[4];
            #pragma unroll
            for (int i = 0; i < 8; i++) a[i] = As[kk * 32 + ty * 8 + i];
            #pragma unroll
            for (int j = 0; j < 4; j++) bb[j] = Bs[kk * 256 + tx + 64 * j];
            #pragma unroll
            for (int i = 0; i < 8; i++)
                #pragma unroll
                for (int j = 0; j < 4; j++) ac0[i][j] += a[i] * bb[j];
        }
    }
    #pragma unroll
    for (int j = 0; j < 4; j++) {
        float bv = lowb[tx + 64 * j];
        #pragma unroll
        for (int i = 0; i < 8; i++)
            kt[(ty * 8 + i) * 256 + tx + 64 * j] = ac0[i][j] + bv;
    }

    // ---- GEMM1: lnH[32x512] = kt @ w1 ----
    float ac1[8][8];
    #pragma unroll
    for (int i = 0; i < 8; i++)
        #pragma unroll
        for (int j = 0; j < 8; j++) ac1[i][j] = 0.f;

    for (int k0 = 0; k0 < 256; k0 += 16) {
        __syncthreads();   // also orders kt writes before reads
        for (int i = tid; i < 2048; i += 256) {
            int kk = i >> 7, cp = (i & 127) << 2;
            *(float4*)(Bs + kk * 512 + cp) =
                *(const float4*)(w1 + (size_t)(k0 + kk) * 512 + cp);
        }
        __syncthreads();
        #pragma unroll
        for (int kk = 0; kk < 16; kk++) {
            float a[8], bb[8];
            #pragma unroll
            for (int i = 0; i < 8; i++) a[i] = kt[(ty * 8 + i) * 256 + k0 + kk];
            #pragma unroll
            for (int j = 0; j < 8; j++) bb[j] = Bs[kk * 512 + tx + 64 * j];
            #pragma unroll
            for (int i = 0; i < 8; i++)
                #pragma unroll
                for (int j = 0; j < 8; j++) ac1[i][j] += a[i] * bb[j];
        }
    }
    #pragma unroll
    for (int j = 0; j < 8; j++) {
        float bv = b1[tx + 64 * j];
        #pragma unroll
        for (int i = 0; i < 8; i++)
            lnH[(ty * 8 + i) * 512 + tx + 64 * j] = ac1[i][j] + bv;
    }
    __syncthreads();

    // ---- LN ----
    for (int rr = 0; rr < 4; rr++) {
        int r = warp * 4 + rr;
        float s = 0.f;
        #pragma unroll
        for (int i = 0; i < 16; i++) s += lnH[r * 512 + lane + 32 * i];
        #pragma unroll
        for (int off = 16; off > 0; off >>= 1) s += __shfl_xor_sync(0xffffffffu, s, off);
        float m = s * (1.0f / 512.0f);
        float v = 0.f;
        #pragma unroll
        for (int i = 0; i < 16; i++) {
            float d = lnH[r * 512 + lane + 32 * i] - m; v += d * d;
        }
        #pragma unroll
        for (int off = 16; off > 0; off >>= 1) v += __shfl_xor_sync(0xffffffffu, v, off);
        float inv = rsqrtf(v * (1.0f / 512.0f) + 1e-5f);
        #pragma unroll
        for (int i = 0; i < 16; i++) {
            int c = lane + 32 * i;
            float x = lnH[r * 512 + c];
            lnH[r * 512 + c] = (x - m) * inv * lnw[c] + lnb[c];
        }
    }
    __syncthreads();

    // ---- GEMM2 + sigmoid -> g_gate ----
    float ac2[8][4];
    #pragma unroll
    for (int i = 0; i < 8; i++)
        #pragma unroll
        for (int j = 0; j < 4; j++) ac2[i][j] = 0.f;

    for (int k0 = 0; k0 < 512; k0 += 16) {
        __syncthreads();
        for (int i = tid; i < 1024; i += 256) {
            int kk = i >> 6, cp = (i & 63) << 2;
            *(float4*)(Bs + kk * 256 + cp) =
                *(const float4*)(w2 + (size_t)(k0 + kk) * 256 + cp);
        }
        __syncthreads();
        #pragma unroll
        for (int kk = 0; kk < 16; kk++) {
            float a[8], bb[4];
            #pragma unroll
            for (int i = 0; i < 8; i++) a[i] = lnH[(ty * 8 + i) * 512 + k0 + kk];
            #pragma unroll
            for (int j = 0; j < 4; j++) bb[j] = Bs[kk * 256 + tx + 64 * j];
            #pragma unroll
            for (int i = 0; i < 8; i++)
                #pragma unroll
                for (int j = 0; j < 4; j++) ac2[i][j] += a[i] * bb[j];
        }
    }
    #pragma unroll
    for (int i = 0; i < 8; i++) {
        #pragma unroll
        for (int j = 0; j < 4; j++) {
            int c = tx + 64 * j;
            float x = ac2[i][j] + b2[c];
            g_gate[(size_t)(row0 + ty * 8 + i) * 256 + c] = 1.0f / (1.0f + expf(-x));
        }
    }
}

// ---------------------------------------------------------------------------
// Kernel 5: compose. One thread per 2x2 output block; recompute Haar bands.
// ---------------------------------------------------------------------------
__global__ __launch_bounds__(256) void k_compose(const float* __restrict__ xb,
                                                 float* __restrict__ out) {
    int blk = blockIdx.x;
    int rg = blk & 15;
    int plane = blk >> 4;            // b*256 + c
    int b = plane >> 8;
    int c = plane & 255;
    int tid = threadIdx.x;
    int px = tid & 63;
    int py = rg * 4 + (tid >> 6);

    const float* p = xb + (size_t)plane * (IMG_H * IMG_W)
                        + (size_t)(2 * py) * IMG_W + 2 * px;
    float2 t0 = *(const float2*)p;
    float2 b0 = *(const float2*)(p + IMG_W);
    float a = (t0.x + t0.y + b0.x + b0.y) * 0.25f;
    float h = (t0.x - t0.y + b0.x - b0.y) * 0.25f;
    float v = (t0.x + t0.y - b0.x - b0.y) * 0.25f;
    float d = (t0.x - t0.y - b0.x + b0.y) * 0.25f;

    int tk = b * 1024 + (py >> 1) * 32 + (px >> 1);
    float ah = g_alpha[tk];
    float av = g_alpha[TOKS_HF + tk];
    float ad = g_alpha[2 * TOKS_HF + tk];
    float g  = g_gate[(size_t)(b * 256 + (py >> 2) * 16 + (px >> 2)) * 256 + c];

    float ae = a * g, he = h * ah, ve = v * av, de = d * ad;
    float2 o0 = make_float2(ae + he + ve + de, ae - he + ve - de);
    float2 o1 = make_float2(ae + he - ve - de, ae - he - ve + de);

    float* q = out + (size_t)plane * (IMG_H * IMG_W)
                   + (size_t)(2 * py) * IMG_W + 2 * px;
    *(float2*)q = o0;
    *(float2*)(q + IMG_W) = o1;
}

// ---------------------------------------------------------------------------
extern "C" void kernel_launch(void* const* d_in, const int* in_sizes, int n_in,
                              void* d_out, int out_size) {
    const float* xb       = (const float*)d_in[0];
    const float* xs       = (const float*)d_in[1];
    const float* hf_w1    = (const float*)d_in[2];
    const float* hf_b1    = (const float*)d_in[3];
    const float* hf_lnw   = (const float*)d_in[4];
    const float* hf_lnb   = (const float*)d_in[5];
    const float* hf_w2    = (const float*)d_in[6];
    const float* hf_b2    = (const float*)d_in[7];
    const float* hf_prompt= (const float*)d_in[8];
    const float* low_w    = (const float*)d_in[9];
    const float* low_b    = (const float*)d_in[10];
    const float* lf_w1    = (const float*)d_in[11];
    const float* lf_b1    = (const float*)d_in[12];
    const float* lf_lnw   = (const float*)d_in[13];
    const float* lf_lnb   = (const float*)d_in[14];
    const float* lf_w2    = (const float*)d_in[15];
    const float* lf_b2    = (const float*)d_in[16];
    float* out = (float*)d_out;

    cudaFuncSetAttribute(k_hf, cudaFuncAttributeMaxDynamicSharedMemorySize, SMEM_HF_BYTES);
    cudaFuncSetAttribute(k_lf, cudaFuncAttributeMaxDynamicSharedMemorySize, SMEM_LF_BYTES);

    k_zband<<<BATCH * 32, 256>>>(xb);
    k_pool<<<BATCH * 16, 256>>>(xs);
    k_hf<<<ROWS_HF / 32, 256, SMEM_HF_BYTES>>>(hf_w1, hf_b1, hf_lnw, hf_lnb,
                                               hf_w2, hf_b2, hf_prompt);
    k_lf<<<ROWS_LF / 32, 256, SMEM_LF_BYTES>>>(low_w, low_b, lf_w1, lf_b1,
                                               lf_lnw, lf_lnb, lf_w2, lf_b2);
    k_compose<<<BATCH * CB * 16, 256>>>(xb, out);
}

// round 3
// speedup vs baseline: 1.0001x; 1.0001x over previous
#include <cuda_runtime.h>
#include <math.h>

#define BATCH 16
#define CB    256
#define CS    512
#define HID   512
#define IMG_H 128
#define IMG_W 128
#define H2    64
#define W2    64

#define TOKS_HF (BATCH*1024)          // 16384 tokens per band
#define ROWS_HF (3*TOKS_HF)           // 49152
#define ROWS_LF (BATCH*256)           // 4096

// scratch (device globals: no allocations allowed)
__device__ float g_z[(size_t)ROWS_HF*CB];      // 48 MiB  token abs-means, 3 bands
__device__ float g_p[(size_t)ROWS_LF*CS];      // 8 MiB   pooled x_small
__device__ float g_alpha[ROWS_HF];             // per-token alpha (3 bands)
__device__ float g_gate[(size_t)ROWS_LF*CB];   // 4 MiB   per-token per-channel gate

// ---------------------------------------------------------------------------
// Kernel 1: Z tokens from x_big. token(th,tw) covers a 4x4 pixel block.
// CTA = (b, th-row). smem transpose for coalesced writes.
// ---------------------------------------------------------------------------
__global__ __launch_bounds__(256) void k_zband(const float* __restrict__ xb) {
    __shared__ float zs[3][32][65];
    int b   = blockIdx.x >> 5;
    int th  = blockIdx.x & 31;
    int tid = threadIdx.x;
    int lane = tid & 31;      // tw
    int warp = tid >> 5;      // 8 warps
    const float* pb = xb + (size_t)b * CB * IMG_H * IMG_W
                         + (size_t)(th * 4) * IMG_W + lane * 4;
    size_t zrow0 = ((size_t)b * 1024 + th * 32);

    for (int cc = 0; cc < 4; cc++) {          // 4 chunks of 64 channels
        #pragma unroll
        for (int ci = 0; ci < 8; ci++) {
            int cl = warp * 8 + ci;           // 0..63
            int c  = cc * 64 + cl;
            const float* p = pb + (size_t)c * (IMG_H * IMG_W);
            float4 r0 = *(const float4*)(p);
            float4 r1 = *(const float4*)(p + IMG_W);
            float4 r2 = *(const float4*)(p + 2 * IMG_W);
            float4 r3 = *(const float4*)(p + 3 * IMG_W);
            float zh = fabsf(r0.x - r0.y + r1.x - r1.y)
                     + fabsf(r0.z - r0.w + r1.z - r1.w)
                     + fabsf(r2.x - r2.y + r3.x - r3.y)
                     + fabsf(r2.z - r2.w + r3.z - r3.w);
            float zv = fabsf(r0.x + r0.y - r1.x - r1.y)
                     + fabsf(r0.z + r0.w - r1.z - r1.w)
                     + fabsf(r2.x + r2.y - r3.x - r3.y)
                     + fabsf(r2.z + r2.w - r3.z - r3.w);
            float zd = fabsf(r0.x - r0.y - r1.x + r1.y)
                     + fabsf(r0.z - r0.w - r1.z + r1.w)
                     + fabsf(r2.x - r2.y - r3.x + r3.y)
                     + fabsf(r2.z - r2.w - r3.z + r3.w);
            zs[0][lane][cl] = zh * 0.0625f;
            zs[1][lane][cl] = zv * 0.0625f;
            zs[2][lane][cl] = zd * 0.0625f;
        }
        __syncthreads();
        for (int i = tid; i < 3 * 32 * 64; i += 256) {
            int band = i >> 11;
            int rem  = i & 2047;
            int t    = rem >> 6;
            int clx  = rem & 63;
            g_z[(size_t)band * TOKS_HF * CB + (zrow0 + t) * CB + cc * 64 + clx]
                = zs[band][t][clx];
        }
        __syncthreads();
    }
}

// ---------------------------------------------------------------------------
// Kernel 2: pooled x_small  P[b*256+t][s] = mean over 4x4.  CTA = (b, th).
// ---------------------------------------------------------------------------
__global__ __launch_bounds__(256) void k_pool(const float* __restrict__ xs) {
    __shared__ float ps[16][65];
    int b   = blockIdx.x >> 4;
    int th  = blockIdx.x & 15;
    int tid = threadIdx.x;
    int lane = tid & 31;
    int warp = tid >> 5;
    const float* pb = xs + (size_t)b * CS * H2 * W2
                         + (size_t)(th * 4) * W2 + lane * 2;
    size_t prow0 = ((size_t)b * 256 + th * 16);

    for (int cc = 0; cc < 8; cc++) {          // 8 chunks of 64 channels
        #pragma unroll
        for (int ci = 0; ci < 8; ci++) {
            int cl = warp * 8 + ci;
            int c  = cc * 64 + cl;
            const float* p = pb + (size_t)c * (H2 * W2);
            float s = 0.f;
            #pragma unroll
            for (int r = 0; r < 4; r++) {
                float2 v = *(const float2*)(p + r * W2);
                s += v.x + v.y;
            }
            s += __shfl_xor_sync(0xffffffffu, s, 1);
            if ((lane & 1) == 0) ps[lane >> 1][cl] = s * (1.0f / 16.0f);
        }
        __syncthreads();
        for (int i = tid; i < 16 * 64; i += 256) {
            int t = i >> 6, clx = i & 63;
            g_p[(prow0 + t) * CS + cc * 64 + clx] = ps[t][clx];
        }
        __syncthreads();
    }
}

// ---------------------------------------------------------------------------
// Kernel 3: hf fused MLP.  CTA = 32 token rows.
// GEMM1 (K=256,N=512) -> +b1 -> LN -> GEMM2 (K=512,N=256) -> cosine vs prompt
// smem: lnH[32*512] | Bs[16*512] (overlaid by reduce partials) | As[16*32] | npr
// ---------------------------------------------------------------------------
#define SMEM_HF_FLOATS (32*512 + 16*512 + 16*32 + 16)
#define SMEM_HF_BYTES  (SMEM_HF_FLOATS * 4)

__global__ __launch_bounds__(256, 2) void k_hf(
    const float* __restrict__ w1, const float* __restrict__ b1,
    const float* __restrict__ lnw, const float* __restrict__ lnb,
    const float* __restrict__ w2, const float* __restrict__ b2,
    const float* __restrict__ prompt)
{
    extern __shared__ float sm[];
    float* lnH  = sm;                     // 32*512
    float* Bs   = sm + 32 * 512;          // 16*512
    float* As   = Bs + 16 * 512;          // 16*32
    float* s_npr = As + 16 * 32;
    float* dotp = Bs;                     // overlay after GEMM2
    float* nqp  = Bs + 32 * 64;

    int tid = threadIdx.x;
    int lane = tid & 31, warp = tid >> 5;
    int tx = tid & 63, ty = tid >> 6;     // ty in 0..3 (8 rows), tx 0..63
    int row0 = blockIdx.x * 32;

    if (warp == 0) {
        float s = 0.f;
        #pragma unroll
        for (int i = 0; i < 8; i++) { float v = prompt[lane + 32 * i]; s += v * v; }
        #pragma unroll
        for (int off = 16; off > 0; off >>= 1) s += __shfl_xor_sync(0xffffffffu, s, off);
        if (lane == 0) *s_npr = sqrtf(s);
    }

    // ---- GEMM1: [32x512] = Z[32x256] @ w1 ----
    float acc[8][8];
    #pragma unroll
    for (int i = 0; i < 8; i++)
        #pragma unroll
        for (int j = 0; j < 8; j++) acc[i][j] = 0.f;

    for (int k0 = 0; k0 < 256; k0 += 16) {
        __syncthreads();
        if (tid < 128) {
            int m = tid >> 2, kk = (tid & 3) * 4;
            float4 v = *(const float4*)(g_z + (size_t)(row0 + m) * 256 + k0 + kk);
            As[(kk + 0) * 32 + m] = v.x;
            As[(kk + 1) * 32 + m] = v.y;
            As[(kk + 2) * 32 + m] = v.z;
            As[(kk + 3) * 32 + m] = v.w;
        }
        for (int i = tid; i < 2048; i += 256) {
            int kk = i >> 7, cp = (i & 127) << 2;
            *(float4*)(Bs + kk * 512 + cp) =
                *(const float4*)(w1 + (size_t)(k0 + kk) * 512 + cp);
        }
        __syncthreads();
        #pragma unroll
        for (int kk = 0; kk < 16; kk++) {
            float a[8], bb[8];
            #pragma unroll
            for (int i = 0; i < 8; i++) a[i] = As[kk * 32 + ty * 8 + i];
            #pragma unroll
            for (int j = 0; j < 8; j++) bb[j] = Bs[kk * 512 + tx + 64 * j];
            #pragma unroll
            for (int i = 0; i < 8; i++)
                #pragma unroll
                for (int j = 0; j < 8; j++) acc[i][j] += a[i] * bb[j];
        }
    }
    #pragma unroll
    for (int j = 0; j < 8; j++) {
        float bv = b1[tx + 64 * j];
        #pragma unroll
        for (int i = 0; i < 8; i++)
            lnH[(ty * 8 + i) * 512 + tx + 64 * j] = acc[i][j] + bv;
    }
    __syncthreads();

    // ---- LayerNorm per row (two-pass, matches reference) ----
    for (int rr = 0; rr < 4; rr++) {
        int r = warp * 4 + rr;
        float s = 0.f;
        #pragma unroll
        for (int i = 0; i < 16; i++) s += lnH[r * 512 + lane + 32 * i];
        #pragma unroll
        for (int off = 16; off > 0; off >>= 1) s += __shfl_xor_sync(0xffffffffu, s, off);
        float m = s * (1.0f / 512.0f);
        float v = 0.f;
        #pragma unroll
        for (int i = 0; i < 16; i++) {
            float d = lnH[r * 512 + lane + 32 * i] - m; v += d * d;
        }
        #pragma unroll
        for (int off = 16; off > 0; off >>= 1) v += __shfl_xor_sync(0xffffffffu, v, off);
        float inv = rsqrtf(v * (1.0f / 512.0f) + 1e-5f);
        #pragma unroll
        for (int i = 0; i < 16; i++) {
            int c = lane + 32 * i;
            float x = lnH[r * 512 + c];
            lnH[r * 512 + c] = (x - m) * inv * lnw[c] + lnb[c];
        }
    }
    __syncthreads();

    // ---- GEMM2: [32x256] = lnH[32x512] @ w2, fused cosine epilogue ----
    float ac2[8][4];
    #pragma unroll
    for (int i = 0; i < 8; i++)
        #pragma unroll
        for (int j = 0; j < 4; j++) ac2[i][j] = 0.f;

    for (int k0 = 0; k0 < 512; k0 += 16) {
        __syncthreads();
        for (int i = tid; i < 1024; i += 256) {
            int kk = i >> 6, cp = (i & 63) << 2;
            *(float4*)(Bs + kk * 256 + cp) =
                *(const float4*)(w2 + (size_t)(k0 + kk) * 256 + cp);
        }
        __syncthreads();
        #pragma unroll
        for (int kk = 0; kk < 16; kk++) {
            float a[8], bb[4];
            #pragma unroll
            for (int i = 0; i < 8; i++) a[i] = lnH[(ty * 8 + i) * 512 + k0 + kk];
            #pragma unroll
            for (int j = 0; j < 4; j++) bb[j] = Bs[kk * 256 + tx + 64 * j];
            #pragma unroll
            for (int i = 0; i < 8; i++)
                #pragma unroll
                for (int j = 0; j < 4; j++) ac2[i][j] += a[i] * bb[j];
        }
    }
    __syncthreads();   // before overlaying Bs with partials

    #pragma unroll
    for (int i = 0; i < 8; i++) {
        float dsum = 0.f, nsum = 0.f;
        #pragma unroll
        for (int j = 0; j < 4; j++) {
            int c = tx + 64 * j;
            float q = ac2[i][j] + b2[c];
            dsum += q * prompt[c];
            nsum += q * q;
        }
        dotp[(ty * 8 + i) * 64 + tx] = dsum;
        nqp [(ty * 8 + i) * 64 + tx] = nsum;
    }
    __syncthreads();
    for (int rr = 0; rr < 4; rr++) {
        int r = warp * 4 + rr;
        float d = dotp[r * 64 + lane] + dotp[r * 64 + lane + 32];
        float n = nqp [r * 64 + lane] + nqp [r * 64 + lane + 32];
        #pragma unroll
        for (int off = 16; off > 0; off >>= 1) {
            d += __shfl_xor_sync(0xffffffffu, d, off);
            n += __shfl_xor_sync(0xffffffffu, n, off);
        }
        if (lane == 0) {
            float sim = d / (fmaxf(sqrtf(n), 1e-8f) * fmaxf(*s_npr, 1e-8f));
            g_alpha[row0 + r] = fmaxf(sim, 0.0f);
        }
    }
}

// ---------------------------------------------------------------------------
// Kernel 4: lf fused chain. CTA = 32 token rows.
// kt = P @ low_w + low_b ;  h = kt @ w1 + b1 ; LN ; gate = sigmoid(h @ w2 + b2)
// ---------------------------------------------------------------------------
#define SMEM_LF_FLOATS (32*256 + 32*512 + 16*512 + 16*32 + 16)
#define SMEM_LF_BYTES  (SMEM_LF_FLOATS * 4)

__global__ __launch_bounds__(256, 1) void k_lf(
    const float* __restrict__ loww, const float* __restrict__ lowb,
    const float* __restrict__ w1, const float* __restrict__ b1,
    const float* __restrict__ lnw, const float* __restrict__ lnb,
    const float* __restrict__ w2, const float* __restrict__ b2)
{
    extern __shared__ float sm[];
    float* kt  = sm;                         // 32*256
    float* lnH = sm + 32 * 256;              // 32*512
    float* Bs  = lnH + 32 * 512;             // 16*512
    float* As  = Bs + 16 * 512;              // 16*32

    int tid = threadIdx.x;
    int lane = tid & 31, warp = tid >> 5;
    int tx = tid & 63, ty = tid >> 6;
    int row0 = blockIdx.x * 32;

    // ---- GEMM0: kt[32x256] = P[32x512] @ loww ----
    float ac0[8][4];
    #pragma unroll
    for (int i = 0; i < 8; i++)
        #pragma unroll
        for (int j = 0; j < 4; j++) ac0[i][j] = 0.f;

    for (int k0 = 0; k0 < 512; k0 += 16) {
        __syncthreads();
        if (tid < 128) {
            int m = tid >> 2, kk = (tid & 3) * 4;
            float4 v = *(const float4*)(g_p + (size_t)(row0 + m) * 512 + k0 + kk);
            As[(kk + 0) * 32 + m] = v.x;
            As[(kk + 1) * 32 + m] = v.y;
            As[(kk + 2) * 32 + m] = v.z;
            As[(kk + 3) * 32 + m] = v.w;
        }
        for (int i = tid; i < 1024; i += 256) {
            int kk = i >> 6, cp = (i & 63) << 2;
            *(float4*)(Bs + kk * 256 + cp) =
                *(const float4*)(loww + (size_t)(k0 + kk) * 256 + cp);
        }
        __syncthreads();
        #pragma unroll
        for (int kk = 0; kk < 16; kk++) {
            float a[8], bb[4];
            #pragma unroll
            for (int i = 0; i < 8; i++) a[i] = As[kk * 32 + ty * 8 + i];
            #pragma unroll
            for (int j = 0; j < 4; j++) bb[j] = Bs[kk * 256 + tx + 64 * j];
            #pragma unroll
            for (int i = 0; i < 8; i++)
                #pragma unroll
                for (int j = 0; j < 4; j++) ac0[i][j] += a[i] * bb[j];
        }
    }
    #pragma unroll
    for (int j = 0; j < 4; j++) {
        float bv = lowb[tx + 64 * j];
        #pragma unroll
        for (int i = 0; i < 8; i++)
            kt[(ty * 8 + i) * 256 + tx + 64 * j] = ac0[i][j] + bv;
    }

    // ---- GEMM1: lnH[32x512] = kt @ w1 ----
    float ac1[8][8];
    #pragma unroll
    for (int i = 0; i < 8; i++)
        #pragma unroll
        for (int j = 0; j < 8; j++) ac1[i][j] = 0.f;

    for (int k0 = 0; k0 < 256; k0 += 16) {
        __syncthreads();   // also orders kt writes before reads
        for (int i = tid; i < 2048; i += 256) {
            int kk = i >> 7, cp = (i & 127) << 2;
            *(float4*)(Bs + kk * 512 + cp) =
                *(const float4*)(w1 + (size_t)(k0 + kk) * 512 + cp);
        }
        __syncthreads();
        #pragma unroll
        for (int kk = 0; kk < 16; kk++) {
            float a[8], bb[8];
            #pragma unroll
            for (int i = 0; i < 8; i++) a[i] = kt[(ty * 8 + i) * 256 + k0 + kk];
            #pragma unroll
            for (int j = 0; j < 8; j++) bb[j] = Bs[kk * 512 + tx + 64 * j];
            #pragma unroll
            for (int i = 0; i < 8; i++)
                #pragma unroll
                for (int j = 0; j < 8; j++) ac1[i][j] += a[i] * bb[j];
        }
    }
    #pragma unroll
    for (int j = 0; j < 8; j++) {
        float bv = b1[tx + 64 * j];
        #pragma unroll
        for (int i = 0; i < 8; i++)
            lnH[(ty * 8 + i) * 512 + tx + 64 * j] = ac1[i][j] + bv;
    }
    __syncthreads();

    // ---- LN ----
    for (int rr = 0; rr < 4; rr++) {
        int r = warp * 4 + rr;
        float s = 0.f;
        #pragma unroll
        for (int i = 0; i < 16; i++) s += lnH[r * 512 + lane + 32 * i];
        #pragma unroll
        for (int off = 16; off > 0; off >>= 1) s += __shfl_xor_sync(0xffffffffu, s, off);
        float m = s * (1.0f / 512.0f);
        float v = 0.f;
        #pragma unroll
        for (int i = 0; i < 16; i++) {
            float d = lnH[r * 512 + lane + 32 * i] - m; v += d * d;
        }
        #pragma unroll
        for (int off = 16; off > 0; off >>= 1) v += __shfl_xor_sync(0xffffffffu, v, off);
        float inv = rsqrtf(v * (1.0f / 512.0f) + 1e-5f);
        #pragma unroll
        for (int i = 0; i < 16; i++) {
            int c = lane + 32 * i;
            float x = lnH[r * 512 + c];
            lnH[r * 512 + c] = (x - m) * inv * lnw[c] + lnb[c];
        }
    }
    __syncthreads();

    // ---- GEMM2 + sigmoid -> g_gate ----
    float ac2[8][4];
    #pragma unroll
    for (int i = 0; i < 8; i++)
        #pragma unroll
        for (int j = 0; j < 4; j++) ac2[i][j] = 0.f;

    for (int k0 = 0; k0 < 512; k0 += 16) {
        __syncthreads();
        for (int i = tid; i < 1024; i += 256) {
            int kk = i >> 6, cp = (i & 63) << 2;
            *(float4*)(Bs + kk * 256 + cp) =
                *(const float4*)(w2 + (size_t)(k0 + kk) * 256 + cp);
        }
        __syncthreads();
        #pragma unroll
        for (int kk = 0; kk < 16; kk++) {
            float a[8], bb[4];
            #pragma unroll
            for (int i = 0; i < 8; i++) a[i] = lnH[(ty * 8 + i) * 512 + k0 + kk];
            #pragma unroll
            for (int j = 0; j < 4; j++) bb[j] = Bs[kk * 256 + tx + 64 * j];
            #pragma unroll
            for (int i = 0; i < 8; i++)
                #pragma unroll
                for (int j = 0; j < 4; j++) ac2[i][j] += a[i] * bb[j];
        }
    }
    #pragma unroll
    for (int i = 0; i < 8; i++) {
        #pragma unroll
        for (int j = 0; j < 4; j++) {
            int c = tx + 64 * j;
            float x = ac2[i][j] + b2[c];
            g_gate[(size_t)(row0 + ty * 8 + i) * 256 + c] = 1.0f / (1.0f + expf(-x));
        }
    }
}

// ---------------------------------------------------------------------------
// Kernel 5: compose. One thread per 2x2 output block; recompute Haar bands.
// ---------------------------------------------------------------------------
__global__ __launch_bounds__(256) void k_compose(const float* __restrict__ xb,
                                                 float* __restrict__ out) {
    int blk = blockIdx.x;
    int rg = blk & 15;
    int plane = blk >> 4;            // b*256 + c
    int b = plane >> 8;
    int c = plane & 255;
    int tid = threadIdx.x;
    int px = tid & 63;
    int py = rg * 4 + (tid >> 6);

    const float* p = xb + (size_t)plane * (IMG_H * IMG_W)
                        + (size_t)(2 * py) * IMG_W + 2 * px;
    float2 t0 = *(const float2*)p;
    float2 b0 = *(const float2*)(p + IMG_W);
    float a = (t0.x + t0.y + b0.x + b0.y) * 0.25f;
    float h = (t0.x - t0.y + b0.x - b0.y) * 0.25f;
    float v = (t0.x + t0.y - b0.x - b0.y) * 0.25f;
    float d = (t0.x - t0.y - b0.x + b0.y) * 0.25f;

    int tk = b * 1024 + (py >> 1) * 32 + (px >> 1);
    float ah = g_alpha[tk];
    float av = g_alpha[TOKS_HF + tk];
    float ad = g_alpha[2 * TOKS_HF + tk];
    float g  = g_gate[(size_t)(b * 256 + (py >> 2) * 16 + (px >> 2)) * 256 + c];

    float ae = a * g, he = h * ah, ve = v * av, de = d * ad;
    float2 o0 = make_float2(ae + he + ve + de, ae - he + ve - de);
    float2 o1 = make_float2(ae + he - ve - de, ae - he - ve + de);

    float* q = out + (size_t)plane * (IMG_H * IMG_W)
                   + (size_t)(2 * py) * IMG_W + 2 * px;
    *(float2*)q = o0;
    *(float2*)(q + IMG_W) = o1;
}

// ---------------------------------------------------------------------------
extern "C" void kernel_launch(void* const* d_in, const int* in_sizes, int n_in,
                              void* d_out, int out_size) {
    const float* xb       = (const float*)d_in[0];
    const float* xs       = (const float*)d_in[1];
    const float* hf_w1    = (const float*)d_in[2];
    const float* hf_b1    = (const float*)d_in[3];
    const float* hf_lnw   = (const float*)d_in[4];
    const float* hf_lnb   = (const float*)d_in[5];
    const float* hf_w2    = (const float*)d_in[6];
    const float* hf_b2    = (const float*)d_in[7];
    const float* hf_prompt= (const float*)d_in[8];
    const float* low_w    = (const float*)d_in[9];
    const float* low_b    = (const float*)d_in[10];
    const float* lf_w1    = (const float*)d_in[11];
    const float* lf_b1    = (const float*)d_in[12];
    const float* lf_lnw   = (const float*)d_in[13];
    const float* lf_lnb   = (const float*)d_in[14];
    const float* lf_w2    = (const float*)d_in[15];
    const float* lf_b2    = (const float*)d_in[16];
    float* out = (float*)d_out;

    cudaFuncSetAttribute(k_hf, cudaFuncAttributeMaxDynamicSharedMemorySize, SMEM_HF_BYTES);
    cudaFuncSetAttribute(k_lf, cudaFuncAttributeMaxDynamicSharedMemorySize, SMEM_LF_BYTES);

    k_zband<<<BATCH * 32, 256>>>(xb);
    k_pool<<<BATCH * 16, 256>>>(xs);
    k_hf<<<ROWS_HF / 32, 256, SMEM_HF_BYTES>>>(hf_w1, hf_b1, hf_lnw, hf_lnb,
                                               hf_w2, hf_b2, hf_prompt);
    k_lf<<<ROWS_LF / 32, 256, SMEM_LF_BYTES>>>(low_w, low_b, lf_w1, lf_b1,
                                               lf_lnw, lf_lnb, lf_w2, lf_b2);
    k_compose<<<BATCH * CB * 16, 256>>>(xb, out);
}